// round 2
// baseline (speedup 1.0000x reference)
#include <cuda_runtime.h>

#define BS 8
#define C 512
#define NR 64
#define NC 64
#define NH 8
#define NB 512               // batches per attention phase = BS*64
#define NX (BS*C*NR*NC)      // 16777216 x elements
#define NM (BS*NR*NC)        // 32768 mask elements
#define SP 68                // smem row stride (floats) in attention kernel

// Scratch (no dynamic allocation allowed)
__device__ float g_xbuf[NX];                 // 67 MB ping buffer for x
__device__ float g_kqv[3u * NB * C * 64];    // 201 MB K,Q,V for one phase

// ---------------------------------------------------------------------------
// Projection kernel: out[p][b][o][n] = sum_c W_p[o][c] * X_b[c][n] + bias_p[o]
// X_b is a view of the grid tensor:  X_b[c][n] = x[base(b) + c*4096 + n*stride_n]
//   col phase: b = bs*64 + r,   base = bs*2M + r*64,  stride_n = 1
//   row phase: b = bs*64 + col, base = bs*2M + col,   stride_n = 64
// CTA: 128 o-rows x 128 n-cols (= 2 batches sharing W), 256 threads, 8x8/thread.
// ---------------------------------------------------------------------------
__global__ __launch_bounds__(256) void proj_kernel(
    const float* __restrict__ xin,
    const float* __restrict__ Wk, const float* __restrict__ Wq, const float* __restrict__ Wv,
    const float* __restrict__ bk, const float* __restrict__ bq, const float* __restrict__ bv,
    int stride_n, float* __restrict__ kqv)
{
    const int p = blockIdx.z;
    const float* __restrict__ W  = (p == 0) ? Wk : ((p == 1) ? Wq : Wv);
    const float* __restrict__ Bv = (p == 0) ? bk : ((p == 1) ? bq : bv);
    const int o0 = blockIdx.y << 7;      // 0,128,256,384
    const int b0 = blockIdx.x << 1;      // batch pair
    const int t  = threadIdx.x;
    const int tx = t & 15, ty = t >> 4;

    size_t base0, base1;
    {
        int bsA = b0 >> 6, idxA = b0 & 63;
        base0 = (size_t)bsA * (C * NR * NC) +
                (stride_n == 1 ? (size_t)idxA * 64 : (size_t)idxA);
        int b1 = b0 + 1;
        int bsB = b1 >> 6, idxB = b1 & 63;
        base1 = (size_t)bsB * (C * NR * NC) +
                (stride_n == 1 ? (size_t)idxB * 64 : (size_t)idxB);
    }

    __shared__ float Ws[16][132];   // transposed W tile: Ws[c][o]
    __shared__ float Xs[16][132];   // Xs[c][n]  (n in [0,128), two batches)

    float acc[8][8] = {};

    for (int kk = 0; kk < C; kk += 16) {
        // --- load W tile (128 o x 16 c), store transposed ---
        #pragma unroll
        for (int r2 = 0; r2 < 2; ++r2) {
            int f = r2 * 256 + t;
            int o = f >> 2, c4 = (f & 3) << 2;
            const float4 wv = *(const float4*)&W[(size_t)(o0 + o) * C + kk + c4];
            Ws[c4 + 0][o] = wv.x;
            Ws[c4 + 1][o] = wv.y;
            Ws[c4 + 2][o] = wv.z;
            Ws[c4 + 3][o] = wv.w;
        }
        // --- load X tile (16 c x 128 n) ---
        #pragma unroll
        for (int r8 = 0; r8 < 8; ++r8) {
            int e = r8 * 256 + t;
            int c = e >> 7, n = e & 127;
            size_t bb = (n < 64) ? base0 : base1;
            int nl = n & 63;
            Xs[c][n] = xin[bb + (size_t)(kk + c) * 4096 + (size_t)nl * stride_n];
        }
        __syncthreads();

        #pragma unroll
        for (int k = 0; k < 16; ++k) {
            float4 a0 = *(const float4*)&Ws[k][ty << 3];
            float4 a1 = *(const float4*)&Ws[k][(ty << 3) + 4];
            float4 x0 = *(const float4*)&Xs[k][tx << 3];
            float4 x1 = *(const float4*)&Xs[k][(tx << 3) + 4];
            float a[8] = {a0.x, a0.y, a0.z, a0.w, a1.x, a1.y, a1.z, a1.w};
            float xv[8] = {x0.x, x0.y, x0.z, x0.w, x1.x, x1.y, x1.z, x1.w};
            #pragma unroll
            for (int i = 0; i < 8; ++i)
                #pragma unroll
                for (int j = 0; j < 8; ++j)
                    acc[i][j] += a[i] * xv[j];
        }
        __syncthreads();
    }

    // --- store to kqv[p][b][o][n] ---
    const int half = tx >> 3;
    const int bq_idx = b0 + half;
    const int nl0 = (tx << 3) & 63;
    #pragma unroll
    for (int i = 0; i < 8; ++i) {
        int o = o0 + (ty << 3) + i;
        float bb = Bv[o];
        size_t ob = ((size_t)(p * NB + bq_idx) * C + o) * 64 + nl0;
        #pragma unroll
        for (int j = 0; j < 8; ++j)
            kqv[ob + j] = acc[i][j] + bb;
    }
}

// ---------------------------------------------------------------------------
// Attention kernel: one CTA per (batch, head).
// K,Q,V head tiles are 64ch x 64n. logits[k][q] = scale*sum_ch K*Q - maskpen,
// softmax over k, O[ch][q] = sum_k V[ch][k] w[k][q], out = O + x (residual).
// ---------------------------------------------------------------------------
__global__ __launch_bounds__(256) void attn_kernel(
    const float* __restrict__ kqv,
    const float* xin, float* xout,
    const float* __restrict__ masks,
    int stride_n)
{
    const int b = blockIdx.x;
    const int h = blockIdx.y;
    const int t = threadIdx.x;

    extern __shared__ float sm[];
    float* Ksm = sm;                 // [64][SP], reused later for softmax weights
    float* Qsm = sm + 64 * SP;
    float* Vsm = sm + 2 * 64 * SP;   // transposed: Vsm[k][ch]
    __shared__ float Msm[64];

    const size_t kqvb = (size_t)b * (C * 64);
    const float* Kg = kqv + kqvb;
    const float* Qg = kqv + (size_t)NB * C * 64 + kqvb;
    const float* Vg = kqv + (size_t)2 * NB * C * 64 + kqvb;

    #pragma unroll
    for (int i = 0; i < 16; ++i) {
        int e = i * 256 + t;
        int ch = e >> 6, k = e & 63;
        int o = ch * NH + h;
        float kvv = Kg[o * 64 + k];
        float qvv = Qg[o * 64 + k];
        float vvv = Vg[o * 64 + k];
        Ksm[ch * SP + k] = kvv;
        Qsm[ch * SP + k] = qvv;
        Vsm[k * SP + ch] = vvv;
    }
    const int bs = b >> 6, idx = b & 63;
    if (t < 64) {
        Msm[t] = (stride_n == 1) ? masks[bs * 4096 + idx * 64 + t]
                                 : masks[bs * 4096 + t * 64 + idx];
    }
    __syncthreads();

    // --- logits: thread (kg,qg) owns 4x4 tile over (k,q) ---
    const int kg = t & 15, qg = t >> 4;
    const int k0 = kg << 2, q0 = qg << 2;
    float acc[4][4] = {};
    #pragma unroll 8
    for (int ch = 0; ch < 64; ++ch) {
        float4 kv = *(const float4*)&Ksm[ch * SP + k0];
        float4 qv = *(const float4*)&Qsm[ch * SP + q0];
        float kr[4] = {kv.x, kv.y, kv.z, kv.w};
        float qr[4] = {qv.x, qv.y, qv.z, qv.w};
        #pragma unroll
        for (int i = 0; i < 4; ++i)
            #pragma unroll
            for (int j = 0; j < 4; ++j)
                acc[i][j] += kr[i] * qr[j];
    }
    const float scale = 0.044194173824159216f;  // 1/sqrt(512)
    #pragma unroll
    for (int i = 0; i < 4; ++i) {
        float mpen = (1.0f - Msm[k0 + i]) * 1e8f;
        #pragma unroll
        for (int j = 0; j < 4; ++j)
            acc[i][j] = acc[i][j] * scale - mpen;
    }

    // --- softmax over k (4 local + 16-lane shuffle group; lanes share qg) ---
    float w[4][4];
    #pragma unroll
    for (int j = 0; j < 4; ++j) {
        float mx = acc[0][j];
        #pragma unroll
        for (int i = 1; i < 4; ++i) mx = fmaxf(mx, acc[i][j]);
        #pragma unroll
        for (int off = 1; off < 16; off <<= 1)
            mx = fmaxf(mx, __shfl_xor_sync(0xffffffffu, mx, off));
        float s = 0.0f;
        #pragma unroll
        for (int i = 0; i < 4; ++i) {
            w[i][j] = __expf(acc[i][j] - mx);
            s += w[i][j];
        }
        #pragma unroll
        for (int off = 1; off < 16; off <<= 1)
            s += __shfl_xor_sync(0xffffffffu, s, off);
        float inv = 1.0f / s;
        #pragma unroll
        for (int i = 0; i < 4; ++i) w[i][j] *= inv;
    }
    __syncthreads();   // all K/Q reads done; reuse Ksm for weights
    #pragma unroll
    for (int i = 0; i < 4; ++i)
        #pragma unroll
        for (int j = 0; j < 4; ++j)
            Ksm[(k0 + i) * SP + q0 + j] = w[i][j];
    __syncthreads();

    // --- O = V @ W : thread (cg,qg) owns 4x4 tile over (ch,q) ---
    const int cg = t & 15;
    const int ch0 = cg << 2;
    float o2[4][4] = {};
    #pragma unroll 8
    for (int k = 0; k < 64; ++k) {
        float4 vv = *(const float4*)&Vsm[k * SP + ch0];
        float4 wv = *(const float4*)&Ksm[k * SP + q0];
        float vr[4] = {vv.x, vv.y, vv.z, vv.w};
        float wr[4] = {wv.x, wv.y, wv.z, wv.w};
        #pragma unroll
        for (int i = 0; i < 4; ++i)
            #pragma unroll
            for (int j = 0; j < 4; ++j)
                o2[i][j] += vr[i] * wr[j];
    }

    // --- residual write back into grid layout ---
    size_t base = (size_t)bs * (C * NR * NC) +
                  (stride_n == 1 ? (size_t)idx * 64 : (size_t)idx);
    #pragma unroll
    for (int i = 0; i < 4; ++i) {
        int o = (ch0 + i) * NH + h;
        #pragma unroll
        for (int j = 0; j < 4; ++j) {
            size_t a = base + (size_t)o * 4096 + (size_t)(q0 + j) * stride_n;
            xout[a] = o2[i][j] + xin[a];
        }
    }
}

__global__ void copy_masks_kernel(const float* __restrict__ m, float* __restrict__ o)
{
    int i = blockIdx.x * 256 + threadIdx.x;
    if (i < NM) o[i] = m[i];
}

// ---------------------------------------------------------------------------
extern "C" void kernel_launch(void* const* d_in, const int* in_sizes, int n_in,
                              void* d_out, int out_size)
{
    const float* x     = (const float*)d_in[0];
    const float* masks = (const float*)d_in[1];

    // Weight/bias ordering: handle both plausible metadata orders.
    // W[0..5] = colWk,colWq,colWv,rowWk,rowWq,rowWv ; B same order.
    const float* W[6];
    const float* B[6];
    if (n_in >= 14 && in_sizes[3] == 3 * C) {
        // signature order: Wk,bk,Wq,bq,Wv,bv (col then row)
        const int wi[6] = {2, 4, 6, 8, 10, 12};
        const int bi[6] = {3, 5, 7, 9, 11, 13};
        for (int i = 0; i < 6; ++i) {
            W[i] = (const float*)d_in[wi[i]];
            B[i] = (const float*)d_in[bi[i]];
        }
    } else {
        // dict order: weights 2..7 (colK,colQ,colV,rowK,rowQ,rowV), biases 8..13
        for (int i = 0; i < 6; ++i) {
            W[i] = (const float*)d_in[2 + i];
            B[i] = (const float*)d_in[8 + i];
        }
    }

    float* xbuf = nullptr;
    float* kqv  = nullptr;
    cudaGetSymbolAddress((void**)&xbuf, g_xbuf);
    cudaGetSymbolAddress((void**)&kqv,  g_kqv);

    const int SMEMB = 3 * 64 * SP * 4;  // 52224 bytes
    cudaFuncSetAttribute(attn_kernel, cudaFuncAttributeMaxDynamicSharedMemorySize, SMEMB);

    float* xo = (float*)d_out;
    const float* xin = x;
    for (int l = 0; l < 3; ++l) {
        size_t wo = (size_t)l * C * C;
        size_t bo = (size_t)l * C;
        // column attention (attend along nc; stride_n = 1)
        proj_kernel<<<dim3(NB / 2, 4, 3), 256>>>(
            xin, W[0] + wo, W[1] + wo, W[2] + wo,
            B[0] + bo, B[1] + bo, B[2] + bo, 1, kqv);
        attn_kernel<<<dim3(NB, NH), 256, SMEMB>>>(kqv, xin, xbuf, masks, 1);
        xin = xbuf;
        // row attention (attend along nr; stride_n = 64)
        proj_kernel<<<dim3(NB / 2, 4, 3), 256>>>(
            xin, W[3] + wo, W[4] + wo, W[5] + wo,
            B[3] + bo, B[4] + bo, B[5] + bo, 64, kqv);
        float* xout = (l == 2) ? xo : xbuf;
        attn_kernel<<<dim3(NB, NH), 256, SMEMB>>>(kqv, xin, xout, masks, 64);
    }

    if (out_size >= NX + NM) {
        copy_masks_kernel<<<(NM + 255) / 256, 256>>>(masks, xo + NX);
    }
}

// round 3
// speedup vs baseline: 1.6814x; 1.6814x over previous
#include <cuda_runtime.h>

#define BS 8
#define C 512
#define NH 8
#define NB 512                        // batches per attention phase = BS*64
#define NX (BS*C*64*64)               // 16777216
#define NM (BS*64*64)                 // 32768
#define SP 68                         // smem row stride (floats) in attn kernel
#define NBC64 ((size_t)NB * C * 64)   // 16777216

// Scratch (no dynamic allocation allowed)
__device__ float g_xA[NX];            // layout A: [bs][c][nr][nc]
__device__ float g_xB[NX];            // layout B: [bs][c][nc][nr]
__device__ float g_obuf[NBC64];       // attention output O[b][o][q]
__device__ float g_kqv[3 * NBC64];    // K,Q,V for one phase

// ---------------------------------------------------------------------------
// Projection: kqv[p][b][o][n] = sum_c W_p[o][c] * X_b[c][n] + bias_p[o]
// X_b[c][n] = xin[(b>>6)*2M + (b&63)*64 + c*4096 + n]   (always stride-1 in n)
// CTA: 128 o x 128 n (2 batches sharing W), 256 threads, 8x8 per thread.
// ---------------------------------------------------------------------------
__global__ __launch_bounds__(256) void proj_kernel(
    const float* __restrict__ xin,
    const float* __restrict__ Wk, const float* __restrict__ Wq, const float* __restrict__ Wv,
    const float* __restrict__ bkp, const float* __restrict__ bqp, const float* __restrict__ bvp,
    float* __restrict__ kqv)
{
    const int p = blockIdx.z;
    const float* __restrict__ W  = (p == 0) ? Wk : ((p == 1) ? Wq : Wv);
    const float* __restrict__ Bv = (p == 0) ? bkp : ((p == 1) ? bqp : bvp);
    const int o0 = blockIdx.y << 7;
    const int b0 = blockIdx.x << 1;
    const int t  = threadIdx.x;
    const int tx = t & 15, ty = t >> 4;

    const size_t base0 = (size_t)(b0 >> 6) * (C * 4096 / 1) * 1  // bs*2M
                       + (size_t)(b0 & 63) * 64;
    const size_t base1 = (size_t)((b0 + 1) >> 6) * ((size_t)C * 4096)
                       + (size_t)((b0 + 1) & 63) * 64;
    // note: C*4096 = 2097152 elements per bs

    __shared__ float Ws[16][132];   // transposed W tile: Ws[c][o]
    __shared__ float Xs[16][132];   // Xs[c][n]

    float acc[8][8] = {};

    for (int kk = 0; kk < C; kk += 16) {
        // W tile: 128 o x 16 c, stored transposed
        #pragma unroll
        for (int r2 = 0; r2 < 2; ++r2) {
            int f = r2 * 256 + t;
            int o = f >> 2, c4 = (f & 3) << 2;
            const float4 wv = *(const float4*)&W[(size_t)(o0 + o) * C + kk + c4];
            Ws[c4 + 0][o] = wv.x;
            Ws[c4 + 1][o] = wv.y;
            Ws[c4 + 2][o] = wv.z;
            Ws[c4 + 3][o] = wv.w;
        }
        // X tile: 16 c x 128 n, float4 coalesced
        #pragma unroll
        for (int r2 = 0; r2 < 2; ++r2) {
            int f = r2 * 256 + t;
            int c = f >> 5, n4 = f & 31;
            size_t bb = (n4 < 16) ? base0 : base1;
            int nl4 = n4 & 15;
            float4 xv = *(const float4*)&xin[bb + (size_t)(kk + c) * 4096 + nl4 * 4];
            *(float4*)&Xs[c][n4 << 2] = xv;
        }
        __syncthreads();

        #pragma unroll
        for (int k = 0; k < 16; ++k) {
            float4 a0 = *(const float4*)&Ws[k][ty << 3];
            float4 a1 = *(const float4*)&Ws[k][(ty << 3) + 4];
            float4 x0 = *(const float4*)&Xs[k][tx << 3];
            float4 x1 = *(const float4*)&Xs[k][(tx << 3) + 4];
            float a[8]  = {a0.x, a0.y, a0.z, a0.w, a1.x, a1.y, a1.z, a1.w};
            float xv[8] = {x0.x, x0.y, x0.z, x0.w, x1.x, x1.y, x1.z, x1.w};
            #pragma unroll
            for (int i = 0; i < 8; ++i)
                #pragma unroll
                for (int j = 0; j < 8; ++j)
                    acc[i][j] += a[i] * xv[j];
        }
        __syncthreads();
    }

    const int bq_idx = b0 + (tx >> 3);
    const int nl0 = (tx << 3) & 63;
    #pragma unroll
    for (int i = 0; i < 8; ++i) {
        int o = o0 + (ty << 3) + i;
        float bb = Bv[o];
        size_t ob = ((size_t)(p * NB + bq_idx) * C + o) * 64 + nl0;
        #pragma unroll
        for (int j = 0; j < 8; ++j)
            kqv[ob + j] = acc[i][j] + bb;
    }
}

// ---------------------------------------------------------------------------
// Attention: one CTA per (batch, head). Writes pure O (no residual).
// K,Q,V all stored [ch][k] in smem (conflict-free). AV uses warp-per-8-rows.
// ---------------------------------------------------------------------------
__global__ __launch_bounds__(256) void attn_kernel(
    const float* __restrict__ kqv,
    float* __restrict__ obuf,
    const float* __restrict__ masks,
    int maskT)
{
    const int b = blockIdx.x;
    const int h = blockIdx.y;
    const int t = threadIdx.x;

    extern __shared__ float sm[];
    float* Ksm = sm;                 // [64][SP]; reused for softmax weights W[k][q]
    float* Qsm = sm + 64 * SP;
    float* Vsm = sm + 2 * 64 * SP;   // [ch][k]
    __shared__ float Msm[64];

    const size_t kb = (size_t)b * (C * 64);
    const float* __restrict__ Kg = kqv + kb;
    const float* __restrict__ Qg = kqv + NBC64 + kb;
    const float* __restrict__ Vg = kqv + 2 * NBC64 + kb;

    // Load K,Q,V head tiles: rows o = ch*NH + h, 16 float4 per row.
    #pragma unroll
    for (int i = 0; i < 4; ++i) {
        int f = i * 256 + t;
        int ch = f >> 4, k4 = (f & 15) << 2;
        size_t g = (size_t)(ch * NH + h) * 64 + k4;
        float4 kv = *(const float4*)&Kg[g];
        float4 qv = *(const float4*)&Qg[g];
        float4 vv = *(const float4*)&Vg[g];
        *(float4*)&Ksm[ch * SP + k4] = kv;
        *(float4*)&Qsm[ch * SP + k4] = qv;
        *(float4*)&Vsm[ch * SP + k4] = vv;
    }
    const int bs = b >> 6, idx = b & 63;
    if (t < 64) {
        Msm[t] = maskT ? masks[bs * 4096 + t * 64 + idx]
                       : masks[bs * 4096 + idx * 64 + t];
    }
    __syncthreads();

    // Logits: thread (kg,qg) owns 4x4 over (k,q).
    const int kg = t & 15, qg = t >> 4;
    const int k0 = kg << 2, q0l = qg << 2;
    float acc[4][4] = {};
    #pragma unroll 8
    for (int ch = 0; ch < 64; ++ch) {
        float4 kv = *(const float4*)&Ksm[ch * SP + k0];
        float4 qv = *(const float4*)&Qsm[ch * SP + q0l];
        float kr[4] = {kv.x, kv.y, kv.z, kv.w};
        float qr[4] = {qv.x, qv.y, qv.z, qv.w};
        #pragma unroll
        for (int i = 0; i < 4; ++i)
            #pragma unroll
            for (int j = 0; j < 4; ++j)
                acc[i][j] += kr[i] * qr[j];
    }
    const float scale = 0.044194173824159216f;  // 1/sqrt(512)
    #pragma unroll
    for (int i = 0; i < 4; ++i) {
        float mpen = (1.0f - Msm[k0 + i]) * 1e8f;
        #pragma unroll
        for (int j = 0; j < 4; ++j)
            acc[i][j] = acc[i][j] * scale - mpen;
    }

    // Softmax over k: 4 local + 16-lane shuffle groups (lanes share qg).
    float w[4][4];
    #pragma unroll
    for (int j = 0; j < 4; ++j) {
        float mx = acc[0][j];
        #pragma unroll
        for (int i = 1; i < 4; ++i) mx = fmaxf(mx, acc[i][j]);
        #pragma unroll
        for (int off = 1; off < 16; off <<= 1)
            mx = fmaxf(mx, __shfl_xor_sync(0xffffffffu, mx, off));
        float s = 0.0f;
        #pragma unroll
        for (int i = 0; i < 4; ++i) {
            w[i][j] = __expf(acc[i][j] - mx);
            s += w[i][j];
        }
        #pragma unroll
        for (int off = 1; off < 16; off <<= 1)
            s += __shfl_xor_sync(0xffffffffu, s, off);
        float inv = 1.0f / s;
        #pragma unroll
        for (int i = 0; i < 4; ++i) w[i][j] *= inv;
    }
    __syncthreads();   // all K/Q reads done; reuse Ksm for weights W[k][q]
    #pragma unroll
    for (int i = 0; i < 4; ++i)
        #pragma unroll
        for (int j = 0; j < 4; ++j)
            Ksm[(k0 + i) * SP + q0l + j] = w[i][j];
    __syncthreads();

    // O[ch][q] = sum_k V[ch][k] * W[k][q]
    // warp owns 8 ch rows, lanes own 2 q each. V rows broadcast, W lane-contig.
    const int wid = t >> 5, lane = t & 31;
    const int ch0 = wid << 3, q0 = lane << 1;
    float o2[8][2] = {};
    #pragma unroll
    for (int kk = 0; kk < 64; kk += 4) {
        float2 w0 = *(const float2*)&Ksm[(kk + 0) * SP + q0];
        float2 w1 = *(const float2*)&Ksm[(kk + 1) * SP + q0];
        float2 w2 = *(const float2*)&Ksm[(kk + 2) * SP + q0];
        float2 w3 = *(const float2*)&Ksm[(kk + 3) * SP + q0];
        #pragma unroll
        for (int i = 0; i < 8; ++i) {
            float4 v = *(const float4*)&Vsm[(ch0 + i) * SP + kk];
            o2[i][0] += v.x * w0.x + v.y * w1.x;
            o2[i][0] += v.z * w2.x + v.w * w3.x;
            o2[i][1] += v.x * w0.y + v.y * w1.y;
            o2[i][1] += v.z * w2.y + v.w * w3.y;
        }
    }

    // Coalesced O store: obuf[b][o][q]
    const size_t ob = (size_t)b * C * 64;
    #pragma unroll
    for (int i = 0; i < 8; ++i) {
        int o = (ch0 + i) * NH + h;
        *(float2*)&obuf[ob + (size_t)o * 64 + q0] = make_float2(o2[i][0], o2[i][1]);
    }
}

// ---------------------------------------------------------------------------
// Fused transpose + residual: out[bs][c][j][i] = in[bs][c][i][j]
//                                              + O[(bs*64+i)][c][j]
// Works for both phase directions. One CTA per (bs,c) 64x64 tile.
// ---------------------------------------------------------------------------
__global__ __launch_bounds__(256) void addT_kernel(
    const float* __restrict__ in,
    const float* __restrict__ obuf,
    float* __restrict__ out)
{
    const int bc = blockIdx.x;
    const int bs = bc >> 9, c = bc & 511;
    const int t = threadIdx.x;
    __shared__ float sm[64][65];

    const size_t inb = (size_t)bs * ((size_t)C * 4096) + (size_t)c * 4096;

    #pragma unroll
    for (int p = 0; p < 4; ++p) {
        int r = p * 16 + (t >> 4);
        int j4 = (t & 15) << 2;
        float4 xv = *(const float4*)&in[inb + (size_t)r * 64 + j4];
        float4 ov = *(const float4*)&obuf[((size_t)(bs * 64 + r) * C + c) * 64 + j4];
        sm[r][j4 + 0] = xv.x + ov.x;
        sm[r][j4 + 1] = xv.y + ov.y;
        sm[r][j4 + 2] = xv.z + ov.z;
        sm[r][j4 + 3] = xv.w + ov.w;
    }
    __syncthreads();
    #pragma unroll
    for (int p = 0; p < 4; ++p) {
        int j = p * 16 + (t >> 4);
        int i4 = (t & 15) << 2;
        float4 val = make_float4(sm[i4 + 0][j], sm[i4 + 1][j],
                                 sm[i4 + 2][j], sm[i4 + 3][j]);
        *(float4*)&out[inb + (size_t)j * 64 + i4] = val;
    }
}

__global__ void copy_masks_kernel(const float* __restrict__ m, float* __restrict__ o)
{
    int i = blockIdx.x * 256 + threadIdx.x;
    if (i < NM) o[i] = m[i];
}

// ---------------------------------------------------------------------------
extern "C" void kernel_launch(void* const* d_in, const int* in_sizes, int n_in,
                              void* d_out, int out_size)
{
    const float* x     = (const float*)d_in[0];
    const float* masks = (const float*)d_in[1];

    const float* W[6];
    const float* B[6];
    if (n_in >= 14 && in_sizes[3] == 3 * C) {
        // signature order: Wk,bk,Wq,bq,Wv,bv (col then row)
        const int wi[6] = {2, 4, 6, 8, 10, 12};
        const int bi[6] = {3, 5, 7, 9, 11, 13};
        for (int i = 0; i < 6; ++i) {
            W[i] = (const float*)d_in[wi[i]];
            B[i] = (const float*)d_in[bi[i]];
        }
    } else {
        // dict order: weights 2..7, biases 8..13
        for (int i = 0; i < 6; ++i) {
            W[i] = (const float*)d_in[2 + i];
            B[i] = (const float*)d_in[8 + i];
        }
    }

    float *xA, *xB, *obuf, *kqv;
    cudaGetSymbolAddress((void**)&xA,   g_xA);
    cudaGetSymbolAddress((void**)&xB,   g_xB);
    cudaGetSymbolAddress((void**)&obuf, g_obuf);
    cudaGetSymbolAddress((void**)&kqv,  g_kqv);

    const int SMEMB = 3 * 64 * SP * 4;  // 52224 bytes
    cudaFuncSetAttribute(attn_kernel, cudaFuncAttributeMaxDynamicSharedMemorySize, SMEMB);

    float* xo = (float*)d_out;
    const float* xin = x;               // layer-0 input is layout A
    for (int l = 0; l < 3; ++l) {
        size_t wo = (size_t)l * C * C;
        size_t bo = (size_t)l * C;
        // --- column attention (layout A in, layout B out) ---
        proj_kernel<<<dim3(NB / 2, 4, 3), 256>>>(
            xin, W[0] + wo, W[1] + wo, W[2] + wo,
            B[0] + bo, B[1] + bo, B[2] + bo, kqv);
        attn_kernel<<<dim3(NB, NH), 256, SMEMB>>>(kqv, obuf, masks, 0);
        addT_kernel<<<BS * C, 256>>>(xin, obuf, xB);
        // --- row attention (layout B in, layout A out) ---
        proj_kernel<<<dim3(NB / 2, 4, 3), 256>>>(
            xB, W[3] + wo, W[4] + wo, W[5] + wo,
            B[3] + bo, B[4] + bo, B[5] + bo, kqv);
        attn_kernel<<<dim3(NB, NH), 256, SMEMB>>>(kqv, obuf, masks, 1);
        float* xout = (l == 2) ? xo : xA;
        addT_kernel<<<BS * C, 256>>>(xB, obuf, xout);
        xin = xA;
    }

    if (out_size >= NX + NM) {
        copy_masks_kernel<<<(NM + 255) / 256, 256>>>(masks, xo + NX);
    }
}

// round 5
// speedup vs baseline: 2.0495x; 1.2189x over previous
#include <cuda_runtime.h>
#include <mma.h>
#include <cstdint>

using namespace nvcuda;

#define BS 8
#define C 512
#define NH 8
#define NB 512                        // batches per attention phase = BS*64
#define NX (BS*C*64*64)               // 16777216
#define NM (BS*64*64)                 // 32768
#define SP 68                         // smem row stride (floats) in attn kernel
#define NBC64 ((size_t)NB * C * 64)   // 16777216

// Scratch (no dynamic allocation allowed)
__device__ float g_xA[NX];            // layout A: [bs][c][nr][nc]
__device__ float g_xB[NX];            // layout B: [bs][c][nc][nr]
__device__ float g_obuf[NBC64];       // attention output O[b][o][q]
__device__ float g_kqv[3 * NBC64];    // K,Q,V for one phase

// ---------------------------------------------------------------------------
// Tensor-core projection via WMMA tf32 (m16n16k8):
//   kqv[p][b][o][n] = sum_c W_p[o][c] * X_b[c][n]      (bias added in attn)
// X_b[c][n] = xin[(b>>6)*2M + (b&63)*64 + c*4096 + n]  (stride-1 in n)
// CTA: 128 o x 128 n (2 batches share W). 8 warps: warp tile 64m x 32n
// = 4x2 wmma fragments. K=512 in chunks of 32 (4 k-steps of 8).
// ---------------------------------------------------------------------------
__global__ __launch_bounds__(256) void proj_tc_kernel(
    const float* __restrict__ xin,
    const float* __restrict__ Wk, const float* __restrict__ Wq, const float* __restrict__ Wv,
    float* __restrict__ kqv)
{
    const int p = blockIdx.z;
    const float* __restrict__ W = (p == 0) ? Wk : ((p == 1) ? Wq : Wv);
    const int o0 = blockIdx.y << 7;
    const int b0 = blockIdx.x << 1;
    const int t  = threadIdx.x;
    const int w  = t >> 5;
    const int wm = w & 1, wn = w >> 1;     // warp tile: 64(m) x 32(n)

    const size_t base0 = (size_t)(b0 >> 6) * ((size_t)C * 4096) + (size_t)(b0 & 63) * 64;
    const size_t base1 = (size_t)((b0 + 1) >> 6) * ((size_t)C * 4096) + (size_t)((b0 + 1) & 63) * 64;

    __shared__ float Ws[128][40];      // W tile [m][k], pad to 40
    __shared__ float Xs[32][136];      // X tile [k][n], pad to 136

    wmma::fragment<wmma::accumulator, 16, 16, 8, float> acc[4][2];
    #pragma unroll
    for (int mt = 0; mt < 4; ++mt)
        #pragma unroll
        for (int nt = 0; nt < 2; ++nt)
            wmma::fill_fragment(acc[mt][nt], 0.0f);

    for (int kk = 0; kk < C; kk += 32) {
        // ---- fill W tile: 128 rows x 32 cols ----
        #pragma unroll
        for (int r2 = 0; r2 < 4; ++r2) {
            int f = r2 * 256 + t;
            int o = f >> 3, c4 = (f & 7) << 2;
            *(float4*)&Ws[o][c4] = *(const float4*)&W[(size_t)(o0 + o) * C + kk + c4];
        }
        // ---- fill X tile: 32 rows x 128 cols (two batches) ----
        #pragma unroll
        for (int r2 = 0; r2 < 4; ++r2) {
            int f = r2 * 256 + t;
            int k = f >> 5, n4 = (f & 31) << 2;
            size_t bb = (n4 < 64) ? base0 : base1;
            *(float4*)&Xs[k][n4] = *(const float4*)&xin[bb + (size_t)(kk + k) * 4096 + (n4 & 63)];
        }
        __syncthreads();

        #pragma unroll
        for (int ks = 0; ks < 4; ++ks) {
            wmma::fragment<wmma::matrix_a, 16, 16, 8, wmma::precision::tf32, wmma::row_major> af[4];
            wmma::fragment<wmma::matrix_b, 16, 16, 8, wmma::precision::tf32, wmma::row_major> bf[2];
            #pragma unroll
            for (int mt = 0; mt < 4; ++mt) {
                wmma::load_matrix_sync(af[mt], &Ws[(wm << 6) + (mt << 4)][ks << 3], 40);
                #pragma unroll
                for (int i = 0; i < af[mt].num_elements; ++i)
                    af[mt].x[i] = wmma::__float_to_tf32(af[mt].x[i]);
            }
            #pragma unroll
            for (int nt = 0; nt < 2; ++nt) {
                wmma::load_matrix_sync(bf[nt], &Xs[ks << 3][(wn << 5) + (nt << 4)], 136);
                #pragma unroll
                for (int i = 0; i < bf[nt].num_elements; ++i)
                    bf[nt].x[i] = wmma::__float_to_tf32(bf[nt].x[i]);
            }
            #pragma unroll
            for (int mt = 0; mt < 4; ++mt)
                #pragma unroll
                for (int nt = 0; nt < 2; ++nt)
                    wmma::mma_sync(acc[mt][nt], af[mt], bf[nt], acc[mt][nt]);
        }
        __syncthreads();
    }

    // ---- store: each 16x16 tile lands inside one batch (n0 is 16-aligned) ----
    #pragma unroll
    for (int mt = 0; mt < 4; ++mt) {
        int mrow = o0 + (wm << 6) + (mt << 4);
        #pragma unroll
        for (int nt = 0; nt < 2; ++nt) {
            int n0 = (wn << 5) + (nt << 4);
            int bq_idx = b0 + (n0 >> 6);
            int nl0 = n0 & 63;
            size_t obase = ((size_t)(p * NB + bq_idx) * C + mrow) * 64 + nl0;
            wmma::store_matrix_sync(&kqv[obase], acc[mt][nt], 64, wmma::mem_row_major);
        }
    }
}

// ---------------------------------------------------------------------------
// Attention: one CTA per (batch, head). Adds K/Q/V biases during smem fill,
// writes pure O (no residual).
// ---------------------------------------------------------------------------
__global__ __launch_bounds__(256) void attn_kernel(
    const float* __restrict__ kqv,
    float* __restrict__ obuf,
    const float* __restrict__ masks,
    const float* __restrict__ bkv, const float* __restrict__ bqv, const float* __restrict__ bvv,
    int maskT)
{
    const int b = blockIdx.x;
    const int h = blockIdx.y;
    const int t = threadIdx.x;

    extern __shared__ float sm[];
    float* Ksm = sm;                 // [64][SP]; reused for softmax weights W[k][q]
    float* Qsm = sm + 64 * SP;
    float* Vsm = sm + 2 * 64 * SP;   // [ch][k]
    __shared__ float Msm[64];

    const size_t kb = (size_t)b * (C * 64);
    const float* __restrict__ Kg = kqv + kb;
    const float* __restrict__ Qg = kqv + NBC64 + kb;
    const float* __restrict__ Vg = kqv + 2 * NBC64 + kb;

    #pragma unroll
    for (int i = 0; i < 4; ++i) {
        int f = i * 256 + t;
        int ch = f >> 4, k4 = (f & 15) << 2;
        int o = ch * NH + h;
        size_t g = (size_t)o * 64 + k4;
        float kbias = __ldg(&bkv[o]);
        float qbias = __ldg(&bqv[o]);
        float vbias = __ldg(&bvv[o]);
        float4 kv = *(const float4*)&Kg[g];
        float4 qv = *(const float4*)&Qg[g];
        float4 vv = *(const float4*)&Vg[g];
        kv.x += kbias; kv.y += kbias; kv.z += kbias; kv.w += kbias;
        qv.x += qbias; qv.y += qbias; qv.z += qbias; qv.w += qbias;
        vv.x += vbias; vv.y += vbias; vv.z += vbias; vv.w += vbias;
        *(float4*)&Ksm[ch * SP + k4] = kv;
        *(float4*)&Qsm[ch * SP + k4] = qv;
        *(float4*)&Vsm[ch * SP + k4] = vv;
    }
    const int bs = b >> 6, idx = b & 63;
    if (t < 64) {
        Msm[t] = maskT ? masks[bs * 4096 + t * 64 + idx]
                       : masks[bs * 4096 + idx * 64 + t];
    }
    __syncthreads();

    const int kg = t & 15, qg = t >> 4;
    const int k0 = kg << 2, q0l = qg << 2;
    float acc[4][4] = {};
    #pragma unroll 8
    for (int ch = 0; ch < 64; ++ch) {
        float4 kv = *(const float4*)&Ksm[ch * SP + k0];
        float4 qv = *(const float4*)&Qsm[ch * SP + q0l];
        float kr[4] = {kv.x, kv.y, kv.z, kv.w};
        float qr[4] = {qv.x, qv.y, qv.z, qv.w};
        #pragma unroll
        for (int i = 0; i < 4; ++i)
            #pragma unroll
            for (int j = 0; j < 4; ++j)
                acc[i][j] += kr[i] * qr[j];
    }
    const float scale = 0.044194173824159216f;  // 1/sqrt(512)
    #pragma unroll
    for (int i = 0; i < 4; ++i) {
        float mpen = (1.0f - Msm[k0 + i]) * 1e8f;
        #pragma unroll
        for (int j = 0; j < 4; ++j)
            acc[i][j] = acc[i][j] * scale - mpen;
    }

    float wv_[4][4];
    #pragma unroll
    for (int j = 0; j < 4; ++j) {
        float mx = acc[0][j];
        #pragma unroll
        for (int i = 1; i < 4; ++i) mx = fmaxf(mx, acc[i][j]);
        #pragma unroll
        for (int off = 1; off < 16; off <<= 1)
            mx = fmaxf(mx, __shfl_xor_sync(0xffffffffu, mx, off));
        float s = 0.0f;
        #pragma unroll
        for (int i = 0; i < 4; ++i) {
            wv_[i][j] = __expf(acc[i][j] - mx);
            s += wv_[i][j];
        }
        #pragma unroll
        for (int off = 1; off < 16; off <<= 1)
            s += __shfl_xor_sync(0xffffffffu, s, off);
        float inv = 1.0f / s;
        #pragma unroll
        for (int i = 0; i < 4; ++i) wv_[i][j] *= inv;
    }
    __syncthreads();
    #pragma unroll
    for (int i = 0; i < 4; ++i)
        #pragma unroll
        for (int j = 0; j < 4; ++j)
            Ksm[(k0 + i) * SP + q0l + j] = wv_[i][j];
    __syncthreads();

    const int wid = t >> 5, lane = t & 31;
    const int ch0 = wid << 3, q0 = lane << 1;
    float o2[8][2] = {};
    #pragma unroll
    for (int kkk = 0; kkk < 64; kkk += 4) {
        float2 w0 = *(const float2*)&Ksm[(kkk + 0) * SP + q0];
        float2 w1 = *(const float2*)&Ksm[(kkk + 1) * SP + q0];
        float2 w2 = *(const float2*)&Ksm[(kkk + 2) * SP + q0];
        float2 w3 = *(const float2*)&Ksm[(kkk + 3) * SP + q0];
        #pragma unroll
        for (int i = 0; i < 8; ++i) {
            float4 v = *(const float4*)&Vsm[(ch0 + i) * SP + kkk];
            o2[i][0] += v.x * w0.x + v.y * w1.x;
            o2[i][0] += v.z * w2.x + v.w * w3.x;
            o2[i][1] += v.x * w0.y + v.y * w1.y;
            o2[i][1] += v.z * w2.y + v.w * w3.y;
        }
    }

    const size_t ob = (size_t)b * C * 64;
    #pragma unroll
    for (int i = 0; i < 8; ++i) {
        int o = (ch0 + i) * NH + h;
        *(float2*)&obuf[ob + (size_t)o * 64 + q0] = make_float2(o2[i][0], o2[i][1]);
    }
}

// ---------------------------------------------------------------------------
// Fused transpose + residual: out[bs][c][j][i] = in[bs][c][i][j] + O[bs*64+i][c][j]
// ---------------------------------------------------------------------------
__global__ __launch_bounds__(256) void addT_kernel(
    const float* __restrict__ in,
    const float* __restrict__ obuf,
    float* __restrict__ out)
{
    const int bc = blockIdx.x;
    const int bs = bc >> 9, c = bc & 511;
    const int t = threadIdx.x;
    __shared__ float sm[64][65];

    const size_t inb = (size_t)bs * ((size_t)C * 4096) + (size_t)c * 4096;

    #pragma unroll
    for (int p = 0; p < 4; ++p) {
        int r = p * 16 + (t >> 4);
        int j4 = (t & 15) << 2;
        float4 xv = *(const float4*)&in[inb + (size_t)r * 64 + j4];
        float4 ov = *(const float4*)&obuf[((size_t)(bs * 64 + r) * C + c) * 64 + j4];
        sm[r][j4 + 0] = xv.x + ov.x;
        sm[r][j4 + 1] = xv.y + ov.y;
        sm[r][j4 + 2] = xv.z + ov.z;
        sm[r][j4 + 3] = xv.w + ov.w;
    }
    __syncthreads();
    #pragma unroll
    for (int p = 0; p < 4; ++p) {
        int j = p * 16 + (t >> 4);
        int i4 = (t & 15) << 2;
        float4 val = make_float4(sm[i4 + 0][j], sm[i4 + 1][j],
                                 sm[i4 + 2][j], sm[i4 + 3][j]);
        *(float4*)&out[inb + (size_t)j * 64 + i4] = val;
    }
}

__global__ void copy_masks_kernel(const float* __restrict__ m, float* __restrict__ o)
{
    int i = blockIdx.x * 256 + threadIdx.x;
    if (i < NM) o[i] = m[i];
}

// ---------------------------------------------------------------------------
extern "C" void kernel_launch(void* const* d_in, const int* in_sizes, int n_in,
                              void* d_out, int out_size)
{
    const float* x     = (const float*)d_in[0];
    const float* masks = (const float*)d_in[1];

    const float* W[6];
    const float* B[6];
    if (n_in >= 14 && in_sizes[3] == 3 * C) {
        const int wi[6] = {2, 4, 6, 8, 10, 12};
        const int bi[6] = {3, 5, 7, 9, 11, 13};
        for (int i = 0; i < 6; ++i) {
            W[i] = (const float*)d_in[wi[i]];
            B[i] = (const float*)d_in[bi[i]];
        }
    } else {
        for (int i = 0; i < 6; ++i) {
            W[i] = (const float*)d_in[2 + i];
            B[i] = (const float*)d_in[8 + i];
        }
    }

    float *xA, *xB, *obuf, *kqv;
    cudaGetSymbolAddress((void**)&xA,   g_xA);
    cudaGetSymbolAddress((void**)&xB,   g_xB);
    cudaGetSymbolAddress((void**)&obuf, g_obuf);
    cudaGetSymbolAddress((void**)&kqv,  g_kqv);

    const int SMEMB = 3 * 64 * SP * 4;  // 52224 bytes
    cudaFuncSetAttribute(attn_kernel, cudaFuncAttributeMaxDynamicSharedMemorySize, SMEMB);

    float* xo = (float*)d_out;
    const float* xin = x;
    for (int l = 0; l < 3; ++l) {
        size_t wo = (size_t)l * C * C;
        size_t bo = (size_t)l * C;
        // column attention (layout A in, layout B out)
        proj_tc_kernel<<<dim3(NB / 2, 4, 3), 256>>>(
            xin, W[0] + wo, W[1] + wo, W[2] + wo, kqv);
        attn_kernel<<<dim3(NB, NH), 256, SMEMB>>>(
            kqv, obuf, masks, B[0] + bo, B[1] + bo, B[2] + bo, 0);
        addT_kernel<<<BS * C, 256>>>(xin, obuf, xB);
        // row attention (layout B in, layout A out)
        proj_tc_kernel<<<dim3(NB / 2, 4, 3), 256>>>(
            xB, W[3] + wo, W[4] + wo, W[5] + wo, kqv);
        attn_kernel<<<dim3(NB, NH), 256, SMEMB>>>(
            kqv, obuf, masks, B[3] + bo, B[4] + bo, B[5] + bo, 1);
        float* xout = (l == 2) ? xo : xA;
        addT_kernel<<<BS * C, 256>>>(xB, obuf, xout);
        xin = xA;
    }

    if (out_size >= NX + NM) {
        copy_masks_kernel<<<(NM + 255) / 256, 256>>>(masks, xo + NX);
    }
}

// round 7
// speedup vs baseline: 2.3365x; 1.1401x over previous
#include <cuda_runtime.h>
#include <mma.h>
#include <cstdint>

using namespace nvcuda;

#define BS 8
#define C 512
#define NH 8
#define NB 512                        // batches per attention phase = BS*64
#define NX (BS*C*64*64)               // 16777216
#define NM (BS*64*64)                 // 32768
#define SP 68                         // smem row stride (floats) in attn kernel
#define NBC64 ((size_t)NB * C * 64)   // 16777216
#define WCC (3*C*C)                   // elems per weight tensor (L,C,C)

// Scratch (no dynamic allocation allowed)
__device__ float g_xA[NX];            // layout A: [bs][c][nr][nc] (exact)
__device__ float g_xB[NX];            // layout B: [bs][c][nc][nr] (exact)
__device__ float g_xAr[NX];           // tf32-rounded copy of layout-A x
__device__ float g_xBr[NX];           // tf32-rounded copy of layout-B x
__device__ float g_Wr[6 * WCC];       // tf32-rounded weights (6 tensors)
__device__ float g_obuf[NBC64];       // attention output O[b][o][q]
__device__ float g_kqv[3 * NBC64];    // K,Q,V for one phase

__device__ __forceinline__ float tf32r(float v) {
    uint32_t u;
    asm("cvt.rna.tf32.f32 %0, %1;" : "=r"(u) : "f"(v));
    return __uint_as_float(u);
}

__device__ __forceinline__ void cp16(uint32_t saddr, const void* g) {
    asm volatile("cp.async.cg.shared.global [%0], [%1], 16;" :: "r"(saddr), "l"(g));
}
__device__ __forceinline__ void cp_commit() {
    asm volatile("cp.async.commit_group;");
}
template <int N>
__device__ __forceinline__ void cp_wait() {
    asm volatile("cp.async.wait_group %0;" :: "n"(N));
}

// ---------------------------------------------------------------------------
// Prepass: round weights / x to tf32-representable fp32.
// ---------------------------------------------------------------------------
__global__ __launch_bounds__(256) void round_w_kernel(
    const float* __restrict__ w0, const float* __restrict__ w1, const float* __restrict__ w2,
    const float* __restrict__ w3, const float* __restrict__ w4, const float* __restrict__ w5,
    float* __restrict__ out)
{
    int i = blockIdx.x * 256 + threadIdx.x;
    if (i >= 6 * WCC) return;
    int w = i / WCC, r = i - w * WCC;
    const float* src = (w == 0) ? w0 : (w == 1) ? w1 : (w == 2) ? w2
                     : (w == 3) ? w3 : (w == 4) ? w4 : w5;
    out[i] = tf32r(src[r]);
}

__global__ __launch_bounds__(256) void round_x_kernel(
    const float* __restrict__ in, float* __restrict__ out)
{
    int i = blockIdx.x * 256 + threadIdx.x;
    float4 v = *(const float4*)&in[(size_t)i * 4];
    v.x = tf32r(v.x); v.y = tf32r(v.y); v.z = tf32r(v.z); v.w = tf32r(v.w);
    *(float4*)&out[(size_t)i * 4] = v;
}

// ---------------------------------------------------------------------------
// Tensor-core projection (WMMA tf32 m16n16k8), cp.async double-buffered.
//   kqv[p][b][o][n] = sum_c W_p[o][c] * X_b[c][n]   (bias added in attn)
// Inputs already tf32-rounded -> no conversion in this kernel.
// CTA: 128 o x 128 n (2 batches share W). 8 warps, warp tile 64m x 32n.
// Dynamic smem: Ws[2][128][40] + Xs[2][32][136]  (75776 B)
// ---------------------------------------------------------------------------
#define WS_ST 40
#define XS_ST 136
#define WS_STAGE (128 * WS_ST)
#define XS_STAGE (32 * XS_ST)
#define XS_BASE (2 * WS_STAGE)

__global__ __launch_bounds__(256) void proj_tc_kernel(
    const float* __restrict__ xin,
    const float* __restrict__ Wk, const float* __restrict__ Wq, const float* __restrict__ Wv,
    float* __restrict__ kqv)
{
    const int p = blockIdx.z;
    const float* __restrict__ W = (p == 0) ? Wk : ((p == 1) ? Wq : Wv);
    const int o0 = blockIdx.y << 7;
    const int b0 = blockIdx.x << 1;
    const int t  = threadIdx.x;
    const int w  = t >> 5;
    const int wm = w & 1, wn = w >> 1;     // warp tile: 64(m) x 32(n)

    const size_t base0 = (size_t)(b0 >> 6) * ((size_t)C * 4096) + (size_t)(b0 & 63) * 64;
    const size_t base1 = (size_t)((b0 + 1) >> 6) * ((size_t)C * 4096) + (size_t)((b0 + 1) & 63) * 64;

    extern __shared__ float smx[];
    uint32_t sbase;
    asm("{ .reg .u64 tmp; cvta.to.shared.u64 tmp, %1; cvt.u32.u64 %0, tmp; }"
        : "=r"(sbase) : "l"(smx));

    wmma::fragment<wmma::accumulator, 16, 16, 8, float> acc[4][2];
    #pragma unroll
    for (int mt = 0; mt < 4; ++mt)
        #pragma unroll
        for (int nt = 0; nt < 2; ++nt)
            wmma::fill_fragment(acc[mt][nt], 0.0f);

    auto load_stage = [&](int s, int kk) {
        uint32_t wbase = sbase + (uint32_t)(s * WS_STAGE) * 4u;
        #pragma unroll
        for (int r2 = 0; r2 < 4; ++r2) {
            int f = r2 * 256 + t;
            int o = f >> 3, c4 = (f & 7) << 2;
            cp16(wbase + (uint32_t)(o * WS_ST + c4) * 4u,
                 &W[(size_t)(o0 + o) * C + kk + c4]);
        }
        uint32_t xbase = sbase + (uint32_t)(XS_BASE + s * XS_STAGE) * 4u;
        #pragma unroll
        for (int r2 = 0; r2 < 4; ++r2) {
            int f = r2 * 256 + t;
            int k = f >> 5, n4 = (f & 31) << 2;
            size_t bb = (n4 < 64) ? base0 : base1;
            cp16(xbase + (uint32_t)(k * XS_ST + n4) * 4u,
                 &xin[bb + (size_t)(kk + k) * 4096 + (n4 & 63)]);
        }
        cp_commit();
    };

    load_stage(0, 0);
    int s = 0;
    for (int kk = 0; kk < C; kk += 32) {
        if (kk + 32 < C) {
            load_stage(s ^ 1, kk + 32);
            cp_wait<1>();
        } else {
            cp_wait<0>();
        }
        __syncthreads();

        const float* Wsm = smx + s * WS_STAGE;
        const float* Xsm = smx + XS_BASE + s * XS_STAGE;
        #pragma unroll
        for (int ks = 0; ks < 4; ++ks) {
            wmma::fragment<wmma::matrix_a, 16, 16, 8, wmma::precision::tf32, wmma::row_major> af[4];
            wmma::fragment<wmma::matrix_b, 16, 16, 8, wmma::precision::tf32, wmma::row_major> bf[2];
            #pragma unroll
            for (int mt = 0; mt < 4; ++mt)
                wmma::load_matrix_sync(af[mt], &Wsm[((wm << 6) + (mt << 4)) * WS_ST + (ks << 3)], WS_ST);
            #pragma unroll
            for (int nt = 0; nt < 2; ++nt)
                wmma::load_matrix_sync(bf[nt], &Xsm[(ks << 3) * XS_ST + (wn << 5) + (nt << 4)], XS_ST);
            #pragma unroll
            for (int mt = 0; mt < 4; ++mt)
                #pragma unroll
                for (int nt = 0; nt < 2; ++nt)
                    wmma::mma_sync(acc[mt][nt], af[mt], bf[nt], acc[mt][nt]);
        }
        __syncthreads();
        s ^= 1;
    }

    #pragma unroll
    for (int mt = 0; mt < 4; ++mt) {
        int mrow = o0 + (wm << 6) + (mt << 4);
        #pragma unroll
        for (int nt = 0; nt < 2; ++nt) {
            int n0 = (wn << 5) + (nt << 4);
            int bq_idx = b0 + (n0 >> 6);
            int nl0 = n0 & 63;
            size_t obase = ((size_t)(p * NB + bq_idx) * C + mrow) * 64 + nl0;
            wmma::store_matrix_sync(&kqv[obase], acc[mt][nt], 64, wmma::mem_row_major);
        }
    }
}

// ---------------------------------------------------------------------------
// Attention: one CTA per (batch, head). Adds K/Q/V biases during smem fill,
// writes pure O (no residual).
// ---------------------------------------------------------------------------
__global__ __launch_bounds__(256) void attn_kernel(
    const float* __restrict__ kqv,
    float* __restrict__ obuf,
    const float* __restrict__ masks,
    const float* __restrict__ bkv, const float* __restrict__ bqv, const float* __restrict__ bvv,
    int maskT)
{
    const int b = blockIdx.x;
    const int h = blockIdx.y;
    const int t = threadIdx.x;

    extern __shared__ float sm[];
    float* Ksm = sm;                 // [64][SP]; reused for softmax weights W[k][q]
    float* Qsm = sm + 64 * SP;
    float* Vsm = sm + 2 * 64 * SP;   // [ch][k]
    __shared__ float Msm[64];

    const size_t kb = (size_t)b * (C * 64);
    const float* __restrict__ Kg = kqv + kb;
    const float* __restrict__ Qg = kqv + NBC64 + kb;
    const float* __restrict__ Vg = kqv + 2 * NBC64 + kb;

    #pragma unroll
    for (int i = 0; i < 4; ++i) {
        int f = i * 256 + t;
        int ch = f >> 4, k4 = (f & 15) << 2;
        int o = ch * NH + h;
        size_t g = (size_t)o * 64 + k4;
        float kbias = __ldg(&bkv[o]);
        float qbias = __ldg(&bqv[o]);
        float vbias = __ldg(&bvv[o]);
        float4 kv = *(const float4*)&Kg[g];
        float4 qv = *(const float4*)&Qg[g];
        float4 vv = *(const float4*)&Vg[g];
        kv.x += kbias; kv.y += kbias; kv.z += kbias; kv.w += kbias;
        qv.x += qbias; qv.y += qbias; qv.z += qbias; qv.w += qbias;
        vv.x += vbias; vv.y += vbias; vv.z += vbias; vv.w += vbias;
        *(float4*)&Ksm[ch * SP + k4] = kv;
        *(float4*)&Qsm[ch * SP + k4] = qv;
        *(float4*)&Vsm[ch * SP + k4] = vv;
    }
    const int bs = b >> 6, idx = b & 63;
    if (t < 64) {
        Msm[t] = maskT ? masks[bs * 4096 + t * 64 + idx]
                       : masks[bs * 4096 + idx * 64 + t];
    }
    __syncthreads();

    const int kg = t & 15, qg = t >> 4;
    const int k0 = kg << 2, q0l = qg << 2;
    float acc[4][4] = {};
    #pragma unroll 8
    for (int ch = 0; ch < 64; ++ch) {
        float4 kv = *(const float4*)&Ksm[ch * SP + k0];
        float4 qv = *(const float4*)&Qsm[ch * SP + q0l];
        float kr[4] = {kv.x, kv.y, kv.z, kv.w};
        float qr[4] = {qv.x, qv.y, qv.z, qv.w};
        #pragma unroll
        for (int i = 0; i < 4; ++i)
            #pragma unroll
            for (int j = 0; j < 4; ++j)
                acc[i][j] += kr[i] * qr[j];
    }
    const float scale = 0.044194173824159216f;  // 1/sqrt(512)
    #pragma unroll
    for (int i = 0; i < 4; ++i) {
        float mpen = (1.0f - Msm[k0 + i]) * 1e8f;
        #pragma unroll
        for (int j = 0; j < 4; ++j)
            acc[i][j] = acc[i][j] * scale - mpen;
    }

    float wv_[4][4];
    #pragma unroll
    for (int j = 0; j < 4; ++j) {
        float mx = acc[0][j];
        #pragma unroll
        for (int i = 1; i < 4; ++i) mx = fmaxf(mx, acc[i][j]);
        #pragma unroll
        for (int off = 1; off < 16; off <<= 1)
            mx = fmaxf(mx, __shfl_xor_sync(0xffffffffu, mx, off));
        float s = 0.0f;
        #pragma unroll
        for (int i = 0; i < 4; ++i) {
            wv_[i][j] = __expf(acc[i][j] - mx);
            s += wv_[i][j];
        }
        #pragma unroll
        for (int off = 1; off < 16; off <<= 1)
            s += __shfl_xor_sync(0xffffffffu, s, off);
        float inv = 1.0f / s;
        #pragma unroll
        for (int i = 0; i < 4; ++i) wv_[i][j] *= inv;
    }
    __syncthreads();
    #pragma unroll
    for (int i = 0; i < 4; ++i)
        #pragma unroll
        for (int j = 0; j < 4; ++j)
            Ksm[(k0 + i) * SP + q0l + j] = wv_[i][j];
    __syncthreads();

    const int wid = t >> 5, lane = t & 31;
    const int ch0 = wid << 3, q0 = lane << 1;
    float o2[8][2] = {};
    #pragma unroll
    for (int kkk = 0; kkk < 64; kkk += 4) {
        float2 w0 = *(const float2*)&Ksm[(kkk + 0) * SP + q0];
        float2 w1 = *(const float2*)&Ksm[(kkk + 1) * SP + q0];
        float2 w2 = *(const float2*)&Ksm[(kkk + 2) * SP + q0];
        float2 w3 = *(const float2*)&Ksm[(kkk + 3) * SP + q0];
        #pragma unroll
        for (int i = 0; i < 8; ++i) {
            float4 v = *(const float4*)&Vsm[(ch0 + i) * SP + kkk];
            o2[i][0] += v.x * w0.x + v.y * w1.x;
            o2[i][0] += v.z * w2.x + v.w * w3.x;
            o2[i][1] += v.x * w0.y + v.y * w1.y;
            o2[i][1] += v.z * w2.y + v.w * w3.y;
        }
    }

    const size_t ob = (size_t)b * C * 64;
    #pragma unroll
    for (int i = 0; i < 8; ++i) {
        int o = (ch0 + i) * NH + h;
        *(float2*)&obuf[ob + (size_t)o * 64 + q0] = make_float2(o2[i][0], o2[i][1]);
    }
}

// ---------------------------------------------------------------------------
// Fused transpose + residual: out[bs][c][j][i] = in[bs][c][i][j] + O[bs*64+i][c][j]
// Also writes a tf32-rounded copy for the next projection.
// ---------------------------------------------------------------------------
__global__ __launch_bounds__(256) void addT_kernel(
    const float* __restrict__ in,
    const float* __restrict__ obuf,
    float* __restrict__ out,
    float* __restrict__ outR)
{
    const int bc = blockIdx.x;
    const int bs = bc >> 9, c = bc & 511;
    const int t = threadIdx.x;
    __shared__ float sm[64][65];

    const size_t inb = (size_t)bs * ((size_t)C * 4096) + (size_t)c * 4096;

    #pragma unroll
    for (int p = 0; p < 4; ++p) {
        int r = p * 16 + (t >> 4);
        int j4 = (t & 15) << 2;
        float4 xv = *(const float4*)&in[inb + (size_t)r * 64 + j4];
        float4 ov = *(const float4*)&obuf[((size_t)(bs * 64 + r) * C + c) * 64 + j4];
        sm[r][j4 + 0] = xv.x + ov.x;
        sm[r][j4 + 1] = xv.y + ov.y;
        sm[r][j4 + 2] = xv.z + ov.z;
        sm[r][j4 + 3] = xv.w + ov.w;
    }
    __syncthreads();
    #pragma unroll
    for (int p = 0; p < 4; ++p) {
        int j = p * 16 + (t >> 4);
        int i4 = (t & 15) << 2;
        float4 val = make_float4(sm[i4 + 0][j], sm[i4 + 1][j],
                                 sm[i4 + 2][j], sm[i4 + 3][j]);
        *(float4*)&out[inb + (size_t)j * 64 + i4] = val;
        float4 vr = make_float4(tf32r(val.x), tf32r(val.y), tf32r(val.z), tf32r(val.w));
        *(float4*)&outR[inb + (size_t)j * 64 + i4] = vr;
    }
}

__global__ void copy_masks_kernel(const float* __restrict__ m, float* __restrict__ o)
{
    int i = blockIdx.x * 256 + threadIdx.x;
    if (i < NM) o[i] = m[i];
}

// ---------------------------------------------------------------------------
extern "C" void kernel_launch(void* const* d_in, const int* in_sizes, int n_in,
                              void* d_out, int out_size)
{
    const float* x     = (const float*)d_in[0];
    const float* masks = (const float*)d_in[1];

    const float* W[6];
    const float* B[6];
    if (n_in >= 14 && in_sizes[3] == 3 * C) {
        const int wi[6] = {2, 4, 6, 8, 10, 12};
        const int bi[6] = {3, 5, 7, 9, 11, 13};
        for (int i = 0; i < 6; ++i) {
            W[i] = (const float*)d_in[wi[i]];
            B[i] = (const float*)d_in[bi[i]];
        }
    } else {
        for (int i = 0; i < 6; ++i) {
            W[i] = (const float*)d_in[2 + i];
            B[i] = (const float*)d_in[8 + i];
        }
    }

    float *xA, *xB, *xAr, *xBr, *Wr, *obuf, *kqv;
    cudaGetSymbolAddress((void**)&xA,   g_xA);
    cudaGetSymbolAddress((void**)&xB,   g_xB);
    cudaGetSymbolAddress((void**)&xAr,  g_xAr);
    cudaGetSymbolAddress((void**)&xBr,  g_xBr);
    cudaGetSymbolAddress((void**)&Wr,   g_Wr);
    cudaGetSymbolAddress((void**)&obuf, g_obuf);
    cudaGetSymbolAddress((void**)&kqv,  g_kqv);

    const int SMEMB = 3 * 64 * SP * 4;  // 52224 bytes (attn)
    const int PSMEM = (2 * WS_STAGE + 2 * XS_STAGE) * 4;  // 75776 bytes (proj)
    cudaFuncSetAttribute(attn_kernel, cudaFuncAttributeMaxDynamicSharedMemorySize, SMEMB);
    cudaFuncSetAttribute(proj_tc_kernel, cudaFuncAttributeMaxDynamicSharedMemorySize, PSMEM);

    // Prepass: tf32-round weights and layer-0 x
    round_w_kernel<<<(6 * WCC + 255) / 256, 256>>>(
        W[0], W[1], W[2], W[3], W[4], W[5], Wr);
    round_x_kernel<<<NX / 1024, 256>>>(x, xAr);

    float* xo = (float*)d_out;
    const float* xin = x;               // exact x for residual
    const float* xinr = xAr;            // rounded x for proj
    for (int l = 0; l < 3; ++l) {
        size_t wo = (size_t)l * C * C;
        size_t bo = (size_t)l * C;
        // column attention (layout A in, layout B out)
        proj_tc_kernel<<<dim3(NB / 2, 4, 3), 256, PSMEM>>>(
            xinr, Wr + 0 * WCC + wo, Wr + 1 * WCC + wo, Wr + 2 * WCC + wo, kqv);
        attn_kernel<<<dim3(NB, NH), 256, SMEMB>>>(
            kqv, obuf, masks, B[0] + bo, B[1] + bo, B[2] + bo, 0);
        addT_kernel<<<BS * C, 256>>>(xin, obuf, xB, xBr);
        // row attention (layout B in, layout A out)
        proj_tc_kernel<<<dim3(NB / 2, 4, 3), 256, PSMEM>>>(
            xBr, Wr + 3 * WCC + wo, Wr + 4 * WCC + wo, Wr + 5 * WCC + wo, kqv);
        attn_kernel<<<dim3(NB, NH), 256, SMEMB>>>(
            kqv, obuf, masks, B[3] + bo, B[4] + bo, B[5] + bo, 1);
        float* xout = (l == 2) ? xo : xA;
        addT_kernel<<<BS * C, 256>>>(xB, obuf, xout, xAr);
        xin = xA;
        xinr = xAr;
    }

    if (out_size >= NX + NM) {
        copy_masks_kernel<<<(NM + 255) / 256, 256>>>(masks, xo + NX);
    }
}